// round 13
// baseline (speedup 1.0000x reference)
#include <cuda_runtime.h>
#include <cuda_fp16.h>
#include <cstdint>
#include <cstddef>

// ---------------------------------------------------------------------------
// PerceiverAttention: fp16 mma.sync GEMMs + fp16 flash-attention.
// R13: kv GEMM gets a 128x256 tile (512 thr, 16 warps) to cut L2 traffic
//      2GB -> 1.5GB (intensity 52 -> 85 FLOP/B). q/out keep 128x128.
//   B=16, S=2048, M=128, DIM=1024, HEADS=16, DIM_HEAD=64, INNER=1024
// ---------------------------------------------------------------------------

#define DIMC     1024
#define BATCH    16
#define SEQ      2048
#define NLAT     128
#define HEADS    16
#define DHEAD    64
#define INNER    1024
#define LNEPS    1e-5f
#define GK       1024

__device__ __half g_xn [(size_t)BATCH * SEQ * DIMC];
__device__ __half g_ln [(size_t)BATCH * NLAT * DIMC];
__device__ __half g_kv [(size_t)BATCH * SEQ * 2 * INNER];
__device__ __half g_q  [(size_t)BATCH * NLAT * INNER];
__device__ __half g_att[(size_t)BATCH * NLAT * INNER];
__device__ __half g_wq [(size_t)INNER * DIMC];
__device__ __half g_wkv[(size_t)2 * INNER * DIMC];
__device__ __half g_wo [(size_t)DIMC * INNER];

// ---------------------------------------------------------------------------
// helpers
// ---------------------------------------------------------------------------
__device__ __forceinline__ void mma_fp16(
    float* c, const uint32_t* a, const uint32_t* b)
{
    asm volatile(
        "mma.sync.aligned.m16n8k16.row.col.f32.f16.f16.f32 "
        "{%0,%1,%2,%3}, {%4,%5,%6,%7}, {%8,%9}, {%0,%1,%2,%3};"
        : "+f"(c[0]), "+f"(c[1]), "+f"(c[2]), "+f"(c[3])
        : "r"(a[0]), "r"(a[1]), "r"(a[2]), "r"(a[3]), "r"(b[0]), "r"(b[1]));
}

#define LDSM_X4(r0, r1, r2, r3, addr) \
    asm volatile("ldmatrix.sync.aligned.m8n8.x4.shared.b16 {%0,%1,%2,%3}, [%4];" \
        : "=r"(r0), "=r"(r1), "=r"(r2), "=r"(r3) : "r"(addr))

#define LDSM_X4_T(r0, r1, r2, r3, addr) \
    asm volatile("ldmatrix.sync.aligned.m8n8.x4.trans.shared.b16 {%0,%1,%2,%3}, [%4];" \
        : "=r"(r0), "=r"(r1), "=r"(r2), "=r"(r3) : "r"(addr))

__device__ __forceinline__ uint32_t h2u(__half2 h) {
    return *reinterpret_cast<uint32_t*>(&h);
}

// ===========================================================================
// fp32 -> fp16 weight conversion
// ===========================================================================
__global__ __launch_bounds__(256) void h_convert_kernel(
    const float4* __restrict__ src, uint2* __restrict__ dst)
{
    int i = blockIdx.x * 256 + threadIdx.x;
    float4 v = src[i];
    uint2 o;
    o.x = h2u(__floats2half2_rn(v.x, v.y));
    o.y = h2u(__floats2half2_rn(v.z, v.w));
    dst[i] = o;
}

// ===========================================================================
// LayerNorm (1024) -> fp16. One block (256 threads) per row.
// ===========================================================================
__global__ __launch_bounds__(256) void ln_kernel(
    const float* __restrict__ X, const float* __restrict__ G,
    const float* __restrict__ Bv, __half* __restrict__ Y)
{
    const int row = blockIdx.x;
    const int t = threadIdx.x;
    const float4* xr = (const float4*)(X + (size_t)row * DIMC);
    float4 v = xr[t];

    float s = v.x + v.y + v.z + v.w;
    float q = v.x * v.x + v.y * v.y + v.z * v.z + v.w * v.w;
    #pragma unroll
    for (int o = 16; o > 0; o >>= 1) {
        s += __shfl_xor_sync(0xffffffffu, s, o);
        q += __shfl_xor_sync(0xffffffffu, q, o);
    }
    __shared__ float rs[8], rq[8];
    __shared__ float s_mu, s_r;
    if ((t & 31) == 0) { rs[t >> 5] = s; rq[t >> 5] = q; }
    __syncthreads();
    if (t == 0) {
        float S = 0.f, Q = 0.f;
        #pragma unroll
        for (int w = 0; w < 8; w++) { S += rs[w]; Q += rq[w]; }
        float mu  = S * (1.f / DIMC);
        float var = Q * (1.f / DIMC) - mu * mu;
        s_mu = mu;
        s_r  = rsqrtf(var + LNEPS);
    }
    __syncthreads();
    const float mu = s_mu, r = s_r;

    float4 g = ((const float4*)G)[t];
    float4 b = ((const float4*)Bv)[t];
    uint2 o;
    o.x = h2u(__floats2half2_rn((v.x - mu) * r * g.x + b.x,
                                (v.y - mu) * r * g.y + b.y));
    o.y = h2u(__floats2half2_rn((v.z - mu) * r * g.z + b.z,
                                (v.w - mu) * r * g.w + b.w));
    ((uint2*)(Y + (size_t)row * DIMC))[t] = o;
}

// ===========================================================================
// Common GEMM constants
// ===========================================================================
#define HSTR 40                          // halves per smem row (32 + 8 pad)
#define KITERS (GK / 32)                 // 32

// ===========================================================================
// 128x128 fp16 mma GEMM (q / out projections). 8 warps, 2 CTAs/SM.
// ===========================================================================
#define TILE_H (128 * HSTR)              // 5120 halves
#define STAGE_H (2 * TILE_H)
#define GEMM_SMEM (4 * STAGE_H * 2)      // 81920 B

__device__ __forceinline__ void stage_copy_h(
    const __half* __restrict__ Ab, const __half* __restrict__ Bb,
    uint32_t sA, uint32_t sB, int k0, int tid)
{
    #pragma unroll
    for (int i = 0; i < 2; i++) {
        const int slot = tid + i * 256;        // 0..511
        const int r = slot >> 2;               // row 0..127
        const int c = slot & 3;                // 8-half chunk 0..3
        const __half* ga = Ab + (size_t)r * GK + k0 + c * 8;
        const __half* gb = Bb + (size_t)r * GK + k0 + c * 8;
        uint32_t da = sA + (uint32_t)(r * HSTR + c * 8) * 2;
        uint32_t db = sB + (uint32_t)(r * HSTR + c * 8) * 2;
        asm volatile("cp.async.cg.shared.global [%0], [%1], 16;" :: "r"(da), "l"(ga));
        asm volatile("cp.async.cg.shared.global [%0], [%1], 16;" :: "r"(db), "l"(gb));
    }
}

template <typename OutT>
__global__ __launch_bounds__(256, 2) void gemm_h(
    const __half* __restrict__ A, const __half* __restrict__ B,
    OutT* __restrict__ C, int Nld)
{
    extern __shared__ __align__(16) __half smh[];
    const int tid  = threadIdx.x;
    const int wid  = tid >> 5;
    const int lane = tid & 31;
    const int wm = wid >> 2;
    const int wn = wid & 3;
    const int rowBase = blockIdx.y * 128;
    const int colBase = blockIdx.x * 128;
    const __half* Ab = A + (size_t)rowBase * GK;
    const __half* Bb = B + (size_t)colBase * GK;

    const uint32_t sbase = (uint32_t)__cvta_generic_to_shared(smh);

    float acc[4][4][4];
    #pragma unroll
    for (int i = 0; i < 4; i++)
        #pragma unroll
        for (int j = 0; j < 4; j++)
            #pragma unroll
            for (int r = 0; r < 4; r++) acc[i][j][r] = 0.f;

    #pragma unroll
    for (int s = 0; s < 3; s++) {
        stage_copy_h(Ab, Bb, sbase + (s * STAGE_H) * 2,
                     sbase + (s * STAGE_H + TILE_H) * 2, s * 32, tid);
        asm volatile("cp.async.commit_group;" ::: "memory");
    }

    const int lr = lane >> 2;
    const int lc = lane & 3;
    const int aRow = wm * 64 + (lane & 15);
    const int aK   = (lane >> 4) << 3;
    const int bRow = wn * 32 + (lane & 7) + ((lane >> 4) << 3);
    const int bK   = ((lane >> 3) & 1) << 3;

    #pragma unroll 1
    for (int t = 0; t < KITERS; t++) {
        if (t < KITERS - 2)
            asm volatile("cp.async.wait_group 2;" ::: "memory");
        else if (t == KITERS - 2)
            asm volatile("cp.async.wait_group 1;" ::: "memory");
        else
            asm volatile("cp.async.wait_group 0;" ::: "memory");
        __syncthreads();

        if (t + 3 < KITERS) {
            const int s2 = (t + 3) & 3;
            stage_copy_h(Ab, Bb, sbase + (s2 * STAGE_H) * 2,
                         sbase + (s2 * STAGE_H + TILE_H) * 2, (t + 3) * 32, tid);
            asm volatile("cp.async.commit_group;" ::: "memory");
        }

        const uint32_t sAs = sbase + ((t & 3) * STAGE_H) * 2;
        const uint32_t sBs = sAs + TILE_H * 2;

        #pragma unroll
        for (int kk = 0; kk < 2; kk++) {
            const int k16 = kk * 16;
            uint32_t a[4][4], b[4][2];
            #pragma unroll
            for (int mt = 0; mt < 4; mt++) {
                uint32_t ad = sAs + (uint32_t)((aRow + mt * 16) * HSTR + k16 + aK) * 2;
                LDSM_X4(a[mt][0], a[mt][1], a[mt][2], a[mt][3], ad);
            }
            #pragma unroll
            for (int g = 0; g < 2; g++) {
                uint32_t bd = sBs + (uint32_t)((bRow + g * 16) * HSTR + k16 + bK) * 2;
                LDSM_X4(b[2 * g][0], b[2 * g][1], b[2 * g + 1][0], b[2 * g + 1][1], bd);
            }
            #pragma unroll
            for (int mt = 0; mt < 4; mt++)
                #pragma unroll
                for (int nt = 0; nt < 4; nt++)
                    mma_fp16(acc[mt][nt], a[mt], b[nt]);
        }
    }

    #pragma unroll
    for (int mt = 0; mt < 4; mt++) {
        #pragma unroll
        for (int nt = 0; nt < 4; nt++) {
            const int row = rowBase + wm * 64 + mt * 16 + lr;
            const int col = colBase + wn * 32 + nt * 8 + 2 * lc;
            if constexpr (sizeof(OutT) == 2) {
                __half* Ch = (__half*)C;
                *(uint32_t*)(Ch + (size_t)row * Nld + col) =
                    h2u(__floats2half2_rn(acc[mt][nt][0], acc[mt][nt][1]));
                *(uint32_t*)(Ch + (size_t)(row + 8) * Nld + col) =
                    h2u(__floats2half2_rn(acc[mt][nt][2], acc[mt][nt][3]));
            } else {
                float* Cf = (float*)C;
                *(float2*)(Cf + (size_t)row * Nld + col) =
                    make_float2(acc[mt][nt][0], acc[mt][nt][1]);
                *(float2*)(Cf + (size_t)(row + 8) * Nld + col) =
                    make_float2(acc[mt][nt][2], acc[mt][nt][3]);
            }
        }
    }
}

// ===========================================================================
// 128x256 fp16 mma GEMM (kv projection). 512 threads, 16 warps, warp 32x64.
// Arithmetic intensity 85 FLOP/L2-byte (vs 52 at 128x128).
// smem: 4 stages x (128+256)x40 halves = 122880 B -> 1 CTA/SM, 16 warps.
// ===========================================================================
#define WA_TILE_H (128 * HSTR)           // 5120
#define WB_TILE_H (256 * HSTR)           // 10240
#define WSTAGE_H (WA_TILE_H + WB_TILE_H) // 15360
#define WGEMM_SMEM (4 * WSTAGE_H * 2)    // 122880 B

__device__ __forceinline__ void stage_copy_w(
    const __half* __restrict__ Ab, const __half* __restrict__ Bb,
    uint32_t sA, uint32_t sB, int k0, int tid)
{
    {   // A: 128 rows x 32 halves = 512 float4
        const int r = tid >> 2;
        const int c = tid & 3;
        const __half* ga = Ab + (size_t)r * GK + k0 + c * 8;
        uint32_t da = sA + (uint32_t)(r * HSTR + c * 8) * 2;
        asm volatile("cp.async.cg.shared.global [%0], [%1], 16;" :: "r"(da), "l"(ga));
    }
    #pragma unroll
    for (int i = 0; i < 2; i++) {        // B: 256 rows x 32 halves = 1024 float4
        const int slot = tid + i * 512;
        const int r = slot >> 2;
        const int c = slot & 3;
        const __half* gb = Bb + (size_t)r * GK + k0 + c * 8;
        uint32_t db = sB + (uint32_t)(r * HSTR + c * 8) * 2;
        asm volatile("cp.async.cg.shared.global [%0], [%1], 16;" :: "r"(db), "l"(gb));
    }
}

__global__ __launch_bounds__(512, 1) void gemm_h_wide(
    const __half* __restrict__ A, const __half* __restrict__ B,
    __half* __restrict__ C, int Nld)
{
    extern __shared__ __align__(16) __half smh[];
    const int tid  = threadIdx.x;
    const int wid  = tid >> 5;
    const int lane = tid & 31;
    const int wm = wid >> 2;                 // 0..3 (32-row bands)
    const int wn = wid & 3;                  // 0..3 (64-col bands)
    const int rowBase = blockIdx.y * 128;
    const int colBase = blockIdx.x * 256;
    const __half* Ab = A + (size_t)rowBase * GK;
    const __half* Bb = B + (size_t)colBase * GK;

    const uint32_t sbase = (uint32_t)__cvta_generic_to_shared(smh);

    float acc[2][8][4];
    #pragma unroll
    for (int i = 0; i < 2; i++)
        #pragma unroll
        for (int j = 0; j < 8; j++)
            #pragma unroll
            for (int r = 0; r < 4; r++) acc[i][j][r] = 0.f;

    #pragma unroll
    for (int s = 0; s < 3; s++) {
        stage_copy_w(Ab, Bb, sbase + (s * WSTAGE_H) * 2,
                     sbase + (s * WSTAGE_H + WA_TILE_H) * 2, s * 32, tid);
        asm volatile("cp.async.commit_group;" ::: "memory");
    }

    const int lr = lane >> 2;
    const int lc = lane & 3;
    const int aRow = wm * 32 + (lane & 15);
    const int aK   = (lane >> 4) << 3;
    const int bRow = wn * 64 + (lane & 7) + ((lane >> 4) << 3);
    const int bK   = ((lane >> 3) & 1) << 3;

    #pragma unroll 1
    for (int t = 0; t < KITERS; t++) {
        if (t < KITERS - 2)
            asm volatile("cp.async.wait_group 2;" ::: "memory");
        else if (t == KITERS - 2)
            asm volatile("cp.async.wait_group 1;" ::: "memory");
        else
            asm volatile("cp.async.wait_group 0;" ::: "memory");
        __syncthreads();

        if (t + 3 < KITERS) {
            const int s2 = (t + 3) & 3;
            stage_copy_w(Ab, Bb, sbase + (s2 * WSTAGE_H) * 2,
                         sbase + (s2 * WSTAGE_H + WA_TILE_H) * 2, (t + 3) * 32, tid);
            asm volatile("cp.async.commit_group;" ::: "memory");
        }

        const uint32_t sAs = sbase + ((t & 3) * WSTAGE_H) * 2;
        const uint32_t sBs = sAs + WA_TILE_H * 2;

        #pragma unroll
        for (int kk = 0; kk < 2; kk++) {
            const int k16 = kk * 16;
            uint32_t a[2][4], b[8][2];
            #pragma unroll
            for (int mt = 0; mt < 2; mt++) {
                uint32_t ad = sAs + (uint32_t)((aRow + mt * 16) * HSTR + k16 + aK) * 2;
                LDSM_X4(a[mt][0], a[mt][1], a[mt][2], a[mt][3], ad);
            }
            #pragma unroll
            for (int g = 0; g < 4; g++) {
                uint32_t bd = sBs + (uint32_t)((bRow + g * 16) * HSTR + k16 + bK) * 2;
                LDSM_X4(b[2 * g][0], b[2 * g][1], b[2 * g + 1][0], b[2 * g + 1][1], bd);
            }
            #pragma unroll
            for (int mt = 0; mt < 2; mt++)
                #pragma unroll
                for (int nt = 0; nt < 8; nt++)
                    mma_fp16(acc[mt][nt], a[mt], b[nt]);
        }
    }

    #pragma unroll
    for (int mt = 0; mt < 2; mt++) {
        #pragma unroll
        for (int nt = 0; nt < 8; nt++) {
            const int row = rowBase + wm * 32 + mt * 16 + lr;
            const int col = colBase + wn * 64 + nt * 8 + 2 * lc;
            *(uint32_t*)(C + (size_t)row * Nld + col) =
                h2u(__floats2half2_rn(acc[mt][nt][0], acc[mt][nt][1]));
            *(uint32_t*)(C + (size_t)(row + 8) * Nld + col) =
                h2u(__floats2half2_rn(acc[mt][nt][2], acc[mt][nt][3]));
        }
    }
}

// ===========================================================================
// fp16 flash attention (unchanged). One block per (b,h), 8 warps, 2 CTAs/SM.
// ===========================================================================
#define SC     64
#define NCHUNK (SEQ / SC)                // 32
#define KVSTR  72
#define KBUF_H (64 * KVSTR)
#define VS_H   (2 * KBUF_H)
#define PS_H   (VS_H + 2 * KBUF_H)
#define PSTR   72
#define ATTN_SMEM ((PS_H + 8 * 16 * PSTR) * 2)   // 55296 B

__global__ __launch_bounds__(256, 2) void attn_mma(
    const __half* __restrict__ Q, const __half* __restrict__ KV,
    __half* __restrict__ O)
{
    extern __shared__ __align__(16) __half smh[];
    const uint32_t sbase = (uint32_t)__cvta_generic_to_shared(smh);
    const int tid  = threadIdx.x;
    const int wid  = tid >> 5;
    const int lane = tid & 31;
    const int lr = lane >> 2;
    const int lc = lane & 3;
    const int b = blockIdx.x >> 4;
    const int h = blockIdx.x & 15;

    const __half* kvb = KV + (size_t)b * SEQ * (2 * INNER) + h * DHEAD;

    uint32_t qa[4][4];
    {
        const __half* Qb = Q + ((size_t)(b * NLAT + wid * 16)) * INNER + h * DHEAD;
        const __half2 s2 = __float2half2_rn(0.125f);
        #pragma unroll
        for (int kk = 0; kk < 4; kk++) {
            const int d = kk * 16 + 2 * lc;
            __half2 v;
            v = *(const __half2*)(Qb + (size_t)lr * INNER + d);       qa[kk][0] = h2u(__hmul2(v, s2));
            v = *(const __half2*)(Qb + (size_t)(lr + 8) * INNER + d); qa[kk][1] = h2u(__hmul2(v, s2));
            v = *(const __half2*)(Qb + (size_t)lr * INNER + d + 8);       qa[kk][2] = h2u(__hmul2(v, s2));
            v = *(const __half2*)(Qb + (size_t)(lr + 8) * INNER + d + 8); qa[kk][3] = h2u(__hmul2(v, s2));
        }
    }

    float o[8][4];
    #pragma unroll
    for (int nt = 0; nt < 8; nt++)
        #pragma unroll
        for (int r = 0; r < 4; r++) o[nt][r] = 0.f;
    float m0 = -1e30f, m1 = -1e30f, l0 = 0.f, l1 = 0.f;

    auto load_chunk = [&](int s0, int buf) {
        #pragma unroll
        for (int i = 0; i < 2; i++) {
            const int slot = tid + i * 256;
            const int r = slot >> 3;
            const int c = slot & 7;
            const __half* gk = kvb + (size_t)(s0 + r) * (2 * INNER) + c * 8;
            uint32_t dk = sbase + (uint32_t)(buf * KBUF_H + r * KVSTR + c * 8) * 2;
            uint32_t dv = sbase + (uint32_t)(VS_H + buf * KBUF_H + r * KVSTR + c * 8) * 2;
            asm volatile("cp.async.cg.shared.global [%0], [%1], 16;" :: "r"(dk), "l"(gk));
            asm volatile("cp.async.cg.shared.global [%0], [%1], 16;" :: "r"(dv), "l"(gk + INNER));
        }
    };

    load_chunk(0, 0);
    asm volatile("cp.async.commit_group;" ::: "memory");

    __half* Ps = smh + PS_H + wid * (16 * PSTR);
    uint32_t* Pu = (uint32_t*)Ps;
    const int kRow = (lane & 7) + ((lane >> 4) << 3);
    const int kK   = ((lane >> 3) & 1) << 3;
    const int vmi = lane >> 3;
    const int vJ  = ((vmi & 1) << 3) + (lane & 7);
    const int vD  = (vmi >> 1) << 3;

    #pragma unroll 1
    for (int c = 0; c < NCHUNK; c++) {
        const int buf = c & 1;
        __syncthreads();
        if (c + 1 < NCHUNK) {
            load_chunk((c + 1) * SC, buf ^ 1);
            asm volatile("cp.async.commit_group;" ::: "memory");
            asm volatile("cp.async.wait_group 1;" ::: "memory");
        } else {
            asm volatile("cp.async.wait_group 0;" ::: "memory");
        }
        __syncthreads();

        const uint32_t Kb = sbase + (uint32_t)(buf * KBUF_H) * 2;
        const uint32_t Vb = sbase + (uint32_t)(VS_H + buf * KBUF_H) * 2;

        float sc[8][4];
        #pragma unroll
        for (int nt = 0; nt < 8; nt++)
            #pragma unroll
            for (int r = 0; r < 4; r++) sc[nt][r] = 0.f;

        #pragma unroll
        for (int kk = 0; kk < 4; kk++) {
            const int k16 = kk * 16;
            uint32_t bb[8][2];
            #pragma unroll
            for (int g = 0; g < 4; g++) {
                uint32_t ad = Kb + (uint32_t)((g * 16 + kRow) * KVSTR + k16 + kK) * 2;
                LDSM_X4(bb[2 * g][0], bb[2 * g][1], bb[2 * g + 1][0], bb[2 * g + 1][1], ad);
            }
            #pragma unroll
            for (int nt = 0; nt < 8; nt++)
                mma_fp16(sc[nt], qa[kk], bb[nt]);
        }

        float mx0 = -1e30f, mx1 = -1e30f;
        #pragma unroll
        for (int nt = 0; nt < 8; nt++) {
            mx0 = fmaxf(mx0, fmaxf(sc[nt][0], sc[nt][1]));
            mx1 = fmaxf(mx1, fmaxf(sc[nt][2], sc[nt][3]));
        }
        #pragma unroll
        for (int off = 1; off <= 2; off <<= 1) {
            mx0 = fmaxf(mx0, __shfl_xor_sync(0xffffffffu, mx0, off));
            mx1 = fmaxf(mx1, __shfl_xor_sync(0xffffffffu, mx1, off));
        }
        const float nm0 = fmaxf(m0, mx0);
        const float nm1 = fmaxf(m1, mx1);
        const float cr0 = __expf(m0 - nm0);
        const float cr1 = __expf(m1 - nm1);
        m0 = nm0; m1 = nm1;

        float rs0 = 0.f, rs1 = 0.f;
        #pragma unroll
        for (int nt = 0; nt < 8; nt++) {
            float p0 = __expf(sc[nt][0] - nm0);
            float p1 = __expf(sc[nt][1] - nm0);
            float p2 = __expf(sc[nt][2] - nm1);
            float p3 = __expf(sc[nt][3] - nm1);
            rs0 += p0 + p1;
            rs1 += p2 + p3;
            Pu[lr * (PSTR / 2) + nt * 4 + lc]       = h2u(__floats2half2_rn(p0, p1));
            Pu[(lr + 8) * (PSTR / 2) + nt * 4 + lc] = h2u(__floats2half2_rn(p2, p3));
        }
        #pragma unroll
        for (int off = 1; off <= 2; off <<= 1) {
            rs0 += __shfl_xor_sync(0xffffffffu, rs0, off);
            rs1 += __shfl_xor_sync(0xffffffffu, rs1, off);
        }
        l0 = l0 * cr0 + rs0;
        l1 = l1 * cr1 + rs1;
        #pragma unroll
        for (int nt = 0; nt < 8; nt++) {
            o[nt][0] *= cr0; o[nt][1] *= cr0;
            o[nt][2] *= cr1; o[nt][3] *= cr1;
        }
        __syncwarp();

        #pragma unroll
        for (int kk = 0; kk < 4; kk++) {
            uint32_t pa[4];
            pa[0] = Pu[lr * (PSTR / 2) + kk * 8 + lc];
            pa[1] = Pu[(lr + 8) * (PSTR / 2) + kk * 8 + lc];
            pa[2] = Pu[lr * (PSTR / 2) + kk * 8 + lc + 4];
            pa[3] = Pu[(lr + 8) * (PSTR / 2) + kk * 8 + lc + 4];
            uint32_t vb[8][2];
            #pragma unroll
            for (int g = 0; g < 4; g++) {
                uint32_t ad = Vb + (uint32_t)((kk * 16 + vJ) * KVSTR + g * 16 + vD) * 2;
                LDSM_X4_T(vb[2 * g][0], vb[2 * g][1], vb[2 * g + 1][0], vb[2 * g + 1][1], ad);
            }
            #pragma unroll
            for (int nt = 0; nt < 8; nt++)
                mma_fp16(o[nt], pa, vb[nt]);
        }
        __syncwarp();
    }

    const float inv0 = 1.f / l0;
    const float inv1 = 1.f / l1;
    __half* Ob = O + ((size_t)(b * NLAT + wid * 16)) * INNER + h * DHEAD;
    #pragma unroll
    for (int nt = 0; nt < 8; nt++) {
        const int col = nt * 8 + 2 * lc;
        *(uint32_t*)(Ob + (size_t)lr * INNER + col) =
            h2u(__floats2half2_rn(o[nt][0] * inv0, o[nt][1] * inv0));
        *(uint32_t*)(Ob + (size_t)(lr + 8) * INNER + col) =
            h2u(__floats2half2_rn(o[nt][2] * inv1, o[nt][3] * inv1));
    }
}

// ===========================================================================
// launch
// ===========================================================================
extern "C" void kernel_launch(void* const* d_in, const int* in_sizes, int n_in,
                              void* d_out, int out_size)
{
    (void)in_sizes; (void)n_in; (void)out_size;
    const float* x   = (const float*)d_in[0];
    const float* lat = (const float*)d_in[1];
    const float* gx  = (const float*)d_in[2];
    const float* bx  = (const float*)d_in[3];
    const float* gl  = (const float*)d_in[4];
    const float* bl  = (const float*)d_in[5];
    const float* Wq  = (const float*)d_in[6];
    const float* Wkv = (const float*)d_in[7];
    const float* Wo  = (const float*)d_in[8];
    float* out = (float*)d_out;

    __half *p_xn, *p_ln, *p_kv, *p_q, *p_att, *p_wq, *p_wkv, *p_wo;
    cudaGetSymbolAddress((void**)&p_xn,  g_xn);
    cudaGetSymbolAddress((void**)&p_ln,  g_ln);
    cudaGetSymbolAddress((void**)&p_kv,  g_kv);
    cudaGetSymbolAddress((void**)&p_q,   g_q);
    cudaGetSymbolAddress((void**)&p_att, g_att);
    cudaGetSymbolAddress((void**)&p_wq,  g_wq);
    cudaGetSymbolAddress((void**)&p_wkv, g_wkv);
    cudaGetSymbolAddress((void**)&p_wo,  g_wo);

    cudaFuncSetAttribute(gemm_h<__half>, cudaFuncAttributeMaxDynamicSharedMemorySize, GEMM_SMEM);
    cudaFuncSetAttribute(gemm_h<float>,  cudaFuncAttributeMaxDynamicSharedMemorySize, GEMM_SMEM);
    cudaFuncSetAttribute(gemm_h_wide,    cudaFuncAttributeMaxDynamicSharedMemorySize, WGEMM_SMEM);
    cudaFuncSetAttribute(attn_mma, cudaFuncAttributeMaxDynamicSharedMemorySize, ATTN_SMEM);

    const int rowsX = BATCH * SEQ;    // 32768
    const int rowsL = BATCH * NLAT;   // 2048

    ln_kernel<<<rowsX, 256>>>(x,   gx, bx, p_xn);
    ln_kernel<<<rowsL, 256>>>(lat, gl, bl, p_ln);

    h_convert_kernel<<<(2 * INNER * DIMC) / 1024, 256>>>((const float4*)Wkv, (uint2*)p_wkv);
    h_convert_kernel<<<(INNER * DIMC) / 1024, 256>>>((const float4*)Wq, (uint2*)p_wq);
    h_convert_kernel<<<(DIMC * INNER) / 1024, 256>>>((const float4*)Wo, (uint2*)p_wo);

    // kv = xn @ Wkv^T : 128x256 tiles (L2-traffic-optimized)
    gemm_h_wide<<<dim3(2 * INNER / 256, rowsX / 128), 512, WGEMM_SMEM>>>(p_xn, p_wkv, p_kv, 2 * INNER);
    // q = ln @ Wq^T : 128x128 tiles
    gemm_h<__half><<<dim3(INNER / 128, rowsL / 128), 256, GEMM_SMEM>>>(p_ln, p_wq, p_q, INNER);

    attn_mma<<<BATCH * HEADS, 256, ATTN_SMEM>>>(p_q, p_kv, p_att);

    gemm_h<float><<<dim3(DIMC / 128, rowsL / 128), 256, GEMM_SMEM>>>(p_att, p_wo, out, DIMC);
}

// round 14
// speedup vs baseline: 1.2512x; 1.2512x over previous
#include <cuda_runtime.h>
#include <cuda_fp16.h>
#include <cstdint>
#include <cstddef>

// ---------------------------------------------------------------------------
// PerceiverAttention: fp16 mma.sync GEMMs + fp16 flash-attention.
// R14: kv GEMM -> BK=64, 3-stage (16 barriers instead of 32), still 128x128
//      tile + 2 CTAs/SM. Converts merged into one launch. Rest = R12 (best).
//   B=16, S=2048, M=128, DIM=1024, HEADS=16, DIM_HEAD=64, INNER=1024
// ---------------------------------------------------------------------------

#define DIMC     1024
#define BATCH    16
#define SEQ      2048
#define NLAT     128
#define HEADS    16
#define DHEAD    64
#define INNER    1024
#define LNEPS    1e-5f
#define GK       1024

__device__ __half g_xn [(size_t)BATCH * SEQ * DIMC];
__device__ __half g_ln [(size_t)BATCH * NLAT * DIMC];
__device__ __half g_kv [(size_t)BATCH * SEQ * 2 * INNER];
__device__ __half g_q  [(size_t)BATCH * NLAT * INNER];
__device__ __half g_att[(size_t)BATCH * NLAT * INNER];
__device__ __half g_wq [(size_t)INNER * DIMC];
__device__ __half g_wkv[(size_t)2 * INNER * DIMC];
__device__ __half g_wo [(size_t)DIMC * INNER];

// ---------------------------------------------------------------------------
// helpers
// ---------------------------------------------------------------------------
__device__ __forceinline__ void mma_fp16(
    float* c, const uint32_t* a, const uint32_t* b)
{
    asm volatile(
        "mma.sync.aligned.m16n8k16.row.col.f32.f16.f16.f32 "
        "{%0,%1,%2,%3}, {%4,%5,%6,%7}, {%8,%9}, {%0,%1,%2,%3};"
        : "+f"(c[0]), "+f"(c[1]), "+f"(c[2]), "+f"(c[3])
        : "r"(a[0]), "r"(a[1]), "r"(a[2]), "r"(a[3]), "r"(b[0]), "r"(b[1]));
}

#define LDSM_X4(r0, r1, r2, r3, addr) \
    asm volatile("ldmatrix.sync.aligned.m8n8.x4.shared.b16 {%0,%1,%2,%3}, [%4];" \
        : "=r"(r0), "=r"(r1), "=r"(r2), "=r"(r3) : "r"(addr))

#define LDSM_X4_T(r0, r1, r2, r3, addr) \
    asm volatile("ldmatrix.sync.aligned.m8n8.x4.trans.shared.b16 {%0,%1,%2,%3}, [%4];" \
        : "=r"(r0), "=r"(r1), "=r"(r2), "=r"(r3) : "r"(addr))

__device__ __forceinline__ uint32_t h2u(__half2 h) {
    return *reinterpret_cast<uint32_t*>(&h);
}

// ===========================================================================
// fp32 -> fp16 weight conversion (all three weights in ONE launch)
// wkv: 524288 float4, wq: 262144, wo: 262144  (total 1048576)
// ===========================================================================
#define N4_WKV 524288
#define N4_WQ  262144
__global__ __launch_bounds__(256) void h_convert3_kernel(
    const float4* __restrict__ wkv, const float4* __restrict__ wq,
    const float4* __restrict__ wo,
    uint2* __restrict__ dkv, uint2* __restrict__ dq, uint2* __restrict__ dwo)
{
    int i = blockIdx.x * 256 + threadIdx.x;
    const float4* src;
    uint2* dst;
    int j;
    if (i < N4_WKV)              { src = wkv; dst = dkv; j = i; }
    else if (i < N4_WKV + N4_WQ) { src = wq;  dst = dq;  j = i - N4_WKV; }
    else                         { src = wo;  dst = dwo; j = i - N4_WKV - N4_WQ; }
    float4 v = src[j];
    uint2 o;
    o.x = h2u(__floats2half2_rn(v.x, v.y));
    o.y = h2u(__floats2half2_rn(v.z, v.w));
    dst[j] = o;
}

// ===========================================================================
// LayerNorm (1024) -> fp16. One block (256 threads) per row.
// ===========================================================================
__global__ __launch_bounds__(256) void ln_kernel(
    const float* __restrict__ X, const float* __restrict__ G,
    const float* __restrict__ Bv, __half* __restrict__ Y)
{
    const int row = blockIdx.x;
    const int t = threadIdx.x;
    const float4* xr = (const float4*)(X + (size_t)row * DIMC);
    float4 v = xr[t];

    float s = v.x + v.y + v.z + v.w;
    float q = v.x * v.x + v.y * v.y + v.z * v.z + v.w * v.w;
    #pragma unroll
    for (int o = 16; o > 0; o >>= 1) {
        s += __shfl_xor_sync(0xffffffffu, s, o);
        q += __shfl_xor_sync(0xffffffffu, q, o);
    }
    __shared__ float rs[8], rq[8];
    __shared__ float s_mu, s_r;
    if ((t & 31) == 0) { rs[t >> 5] = s; rq[t >> 5] = q; }
    __syncthreads();
    if (t == 0) {
        float S = 0.f, Q = 0.f;
        #pragma unroll
        for (int w = 0; w < 8; w++) { S += rs[w]; Q += rq[w]; }
        float mu  = S * (1.f / DIMC);
        float var = Q * (1.f / DIMC) - mu * mu;
        s_mu = mu;
        s_r  = rsqrtf(var + LNEPS);
    }
    __syncthreads();
    const float mu = s_mu, r = s_r;

    float4 g = ((const float4*)G)[t];
    float4 b = ((const float4*)Bv)[t];
    uint2 o;
    o.x = h2u(__floats2half2_rn((v.x - mu) * r * g.x + b.x,
                                (v.y - mu) * r * g.y + b.y));
    o.y = h2u(__floats2half2_rn((v.z - mu) * r * g.z + b.z,
                                (v.w - mu) * r * g.w + b.w));
    ((uint2*)(Y + (size_t)row * DIMC))[t] = o;
}

// ===========================================================================
// 128x128 fp16 mma GEMM, BK=32 (q / out projections). 8 warps, 2 CTAs/SM.
// ===========================================================================
#define HSTR 40
#define KITERS (GK / 32)                 // 32
#define TILE_H (128 * HSTR)
#define STAGE_H (2 * TILE_H)
#define GEMM_SMEM (4 * STAGE_H * 2)      // 81920 B

__device__ __forceinline__ void stage_copy_h(
    const __half* __restrict__ Ab, const __half* __restrict__ Bb,
    uint32_t sA, uint32_t sB, int k0, int tid)
{
    #pragma unroll
    for (int i = 0; i < 2; i++) {
        const int slot = tid + i * 256;
        const int r = slot >> 2;
        const int c = slot & 3;
        const __half* ga = Ab + (size_t)r * GK + k0 + c * 8;
        const __half* gb = Bb + (size_t)r * GK + k0 + c * 8;
        uint32_t da = sA + (uint32_t)(r * HSTR + c * 8) * 2;
        uint32_t db = sB + (uint32_t)(r * HSTR + c * 8) * 2;
        asm volatile("cp.async.cg.shared.global [%0], [%1], 16;" :: "r"(da), "l"(ga));
        asm volatile("cp.async.cg.shared.global [%0], [%1], 16;" :: "r"(db), "l"(gb));
    }
}

template <typename OutT>
__global__ __launch_bounds__(256, 2) void gemm_h(
    const __half* __restrict__ A, const __half* __restrict__ B,
    OutT* __restrict__ C, int Nld)
{
    extern __shared__ __align__(16) __half smh[];
    const int tid  = threadIdx.x;
    const int wid  = tid >> 5;
    const int lane = tid & 31;
    const int wm = wid >> 2;
    const int wn = wid & 3;
    const int rowBase = blockIdx.y * 128;
    const int colBase = blockIdx.x * 128;
    const __half* Ab = A + (size_t)rowBase * GK;
    const __half* Bb = B + (size_t)colBase * GK;

    const uint32_t sbase = (uint32_t)__cvta_generic_to_shared(smh);

    float acc[4][4][4];
    #pragma unroll
    for (int i = 0; i < 4; i++)
        #pragma unroll
        for (int j = 0; j < 4; j++)
            #pragma unroll
            for (int r = 0; r < 4; r++) acc[i][j][r] = 0.f;

    #pragma unroll
    for (int s = 0; s < 3; s++) {
        stage_copy_h(Ab, Bb, sbase + (s * STAGE_H) * 2,
                     sbase + (s * STAGE_H + TILE_H) * 2, s * 32, tid);
        asm volatile("cp.async.commit_group;" ::: "memory");
    }

    const int lr = lane >> 2;
    const int lc = lane & 3;
    const int aRow = wm * 64 + (lane & 15);
    const int aK   = (lane >> 4) << 3;
    const int bRow = wn * 32 + (lane & 7) + ((lane >> 4) << 3);
    const int bK   = ((lane >> 3) & 1) << 3;

    #pragma unroll 1
    for (int t = 0; t < KITERS; t++) {
        if (t < KITERS - 2)
            asm volatile("cp.async.wait_group 2;" ::: "memory");
        else if (t == KITERS - 2)
            asm volatile("cp.async.wait_group 1;" ::: "memory");
        else
            asm volatile("cp.async.wait_group 0;" ::: "memory");
        __syncthreads();

        if (t + 3 < KITERS) {
            const int s2 = (t + 3) & 3;
            stage_copy_h(Ab, Bb, sbase + (s2 * STAGE_H) * 2,
                         sbase + (s2 * STAGE_H + TILE_H) * 2, (t + 3) * 32, tid);
            asm volatile("cp.async.commit_group;" ::: "memory");
        }

        const uint32_t sAs = sbase + ((t & 3) * STAGE_H) * 2;
        const uint32_t sBs = sAs + TILE_H * 2;

        #pragma unroll
        for (int kk = 0; kk < 2; kk++) {
            const int k16 = kk * 16;
            uint32_t a[4][4], b[4][2];
            #pragma unroll
            for (int mt = 0; mt < 4; mt++) {
                uint32_t ad = sAs + (uint32_t)((aRow + mt * 16) * HSTR + k16 + aK) * 2;
                LDSM_X4(a[mt][0], a[mt][1], a[mt][2], a[mt][3], ad);
            }
            #pragma unroll
            for (int g = 0; g < 2; g++) {
                uint32_t bd = sBs + (uint32_t)((bRow + g * 16) * HSTR + k16 + bK) * 2;
                LDSM_X4(b[2 * g][0], b[2 * g][1], b[2 * g + 1][0], b[2 * g + 1][1], bd);
            }
            #pragma unroll
            for (int mt = 0; mt < 4; mt++)
                #pragma unroll
                for (int nt = 0; nt < 4; nt++)
                    mma_fp16(acc[mt][nt], a[mt], b[nt]);
        }
    }

    #pragma unroll
    for (int mt = 0; mt < 4; mt++) {
        #pragma unroll
        for (int nt = 0; nt < 4; nt++) {
            const int row = rowBase + wm * 64 + mt * 16 + lr;
            const int col = colBase + wn * 32 + nt * 8 + 2 * lc;
            if constexpr (sizeof(OutT) == 2) {
                __half* Ch = (__half*)C;
                *(uint32_t*)(Ch + (size_t)row * Nld + col) =
                    h2u(__floats2half2_rn(acc[mt][nt][0], acc[mt][nt][1]));
                *(uint32_t*)(Ch + (size_t)(row + 8) * Nld + col) =
                    h2u(__floats2half2_rn(acc[mt][nt][2], acc[mt][nt][3]));
            } else {
                float* Cf = (float*)C;
                *(float2*)(Cf + (size_t)row * Nld + col) =
                    make_float2(acc[mt][nt][0], acc[mt][nt][1]);
                *(float2*)(Cf + (size_t)(row + 8) * Nld + col) =
                    make_float2(acc[mt][nt][2], acc[mt][nt][3]);
            }
        }
    }
}

// ===========================================================================
// 128x128 fp16 mma GEMM, BK=64, 3 stages (kv projection). 8 warps, 2 CTAs/SM.
// 16 mainloop barriers (vs 32), 64 mma per warp per barrier window.
// smem: 3 x (2 x 128 x 72) halves = 110592 B per CTA; 2 CTAs = 221 KB.
// ===========================================================================
#define H2STR 72                          // 64 + 8 pad halves
#define TILE2_H (128 * H2STR)             // 9216 halves
#define STAGE2_H (2 * TILE2_H)            // 18432 halves (36864 B)
#define GEMM2_SMEM (3 * STAGE2_H * 2)     // 110592 B
#define KITERS2 (GK / 64)                 // 16

__device__ __forceinline__ void stage_copy_h2(
    const __half* __restrict__ Ab, const __half* __restrict__ Bb,
    uint32_t sA, uint32_t sB, int k0, int tid)
{
    #pragma unroll
    for (int i = 0; i < 4; i++) {
        const int slot = tid + i * 256;        // 0..1023
        const int r = slot >> 3;               // row 0..127
        const int c = slot & 7;                // 8-half chunk 0..7
        const __half* ga = Ab + (size_t)r * GK + k0 + c * 8;
        const __half* gb = Bb + (size_t)r * GK + k0 + c * 8;
        uint32_t da = sA + (uint32_t)(r * H2STR + c * 8) * 2;
        uint32_t db = sB + (uint32_t)(r * H2STR + c * 8) * 2;
        asm volatile("cp.async.cg.shared.global [%0], [%1], 16;" :: "r"(da), "l"(ga));
        asm volatile("cp.async.cg.shared.global [%0], [%1], 16;" :: "r"(db), "l"(gb));
    }
}

__global__ __launch_bounds__(256, 2) void gemm_h2(
    const __half* __restrict__ A, const __half* __restrict__ B,
    __half* __restrict__ C, int Nld)
{
    extern __shared__ __align__(16) __half smh[];
    const int tid  = threadIdx.x;
    const int wid  = tid >> 5;
    const int lane = tid & 31;
    const int wm = wid >> 2;
    const int wn = wid & 3;
    const int rowBase = blockIdx.y * 128;
    const int colBase = blockIdx.x * 128;
    const __half* Ab = A + (size_t)rowBase * GK;
    const __half* Bb = B + (size_t)colBase * GK;

    const uint32_t sbase = (uint32_t)__cvta_generic_to_shared(smh);

    float acc[4][4][4];
    #pragma unroll
    for (int i = 0; i < 4; i++)
        #pragma unroll
        for (int j = 0; j < 4; j++)
            #pragma unroll
            for (int r = 0; r < 4; r++) acc[i][j][r] = 0.f;

    // prologue: stages 0, 1
    #pragma unroll
    for (int s = 0; s < 2; s++) {
        stage_copy_h2(Ab, Bb, sbase + (s * STAGE2_H) * 2,
                      sbase + (s * STAGE2_H + TILE2_H) * 2, s * 64, tid);
        asm volatile("cp.async.commit_group;" ::: "memory");
    }

    const int lr = lane >> 2;
    const int lc = lane & 3;
    const int aRow = wm * 64 + (lane & 15);
    const int aK   = (lane >> 4) << 3;
    const int bRow = wn * 32 + (lane & 7) + ((lane >> 4) << 3);
    const int bK   = ((lane >> 3) & 1) << 3;

    int buf = 0;                   // stage t % 3
    #pragma unroll 1
    for (int t = 0; t < KITERS2; t++) {
        if (t < KITERS2 - 1)
            asm volatile("cp.async.wait_group 1;" ::: "memory");
        else
            asm volatile("cp.async.wait_group 0;" ::: "memory");
        __syncthreads();

        if (t + 2 < KITERS2) {
            int nb = buf + 2; if (nb >= 3) nb -= 3;
            stage_copy_h2(Ab, Bb, sbase + (nb * STAGE2_H) * 2,
                          sbase + (nb * STAGE2_H + TILE2_H) * 2, (t + 2) * 64, tid);
            asm volatile("cp.async.commit_group;" ::: "memory");
        }

        const uint32_t sAs = sbase + (buf * STAGE2_H) * 2;
        const uint32_t sBs = sAs + TILE2_H * 2;

        #pragma unroll
        for (int kk = 0; kk < 4; kk++) {
            const int k16 = kk * 16;
            uint32_t a[4][4], b[4][2];
            #pragma unroll
            for (int mt = 0; mt < 4; mt++) {
                uint32_t ad = sAs + (uint32_t)((aRow + mt * 16) * H2STR + k16 + aK) * 2;
                LDSM_X4(a[mt][0], a[mt][1], a[mt][2], a[mt][3], ad);
            }
            #pragma unroll
            for (int g = 0; g < 2; g++) {
                uint32_t bd = sBs + (uint32_t)((bRow + g * 16) * H2STR + k16 + bK) * 2;
                LDSM_X4(b[2 * g][0], b[2 * g][1], b[2 * g + 1][0], b[2 * g + 1][1], bd);
            }
            #pragma unroll
            for (int mt = 0; mt < 4; mt++)
                #pragma unroll
                for (int nt = 0; nt < 4; nt++)
                    mma_fp16(acc[mt][nt], a[mt], b[nt]);
        }
        if (++buf == 3) buf = 0;
    }

    #pragma unroll
    for (int mt = 0; mt < 4; mt++) {
        #pragma unroll
        for (int nt = 0; nt < 4; nt++) {
            const int row = rowBase + wm * 64 + mt * 16 + lr;
            const int col = colBase + wn * 32 + nt * 8 + 2 * lc;
            *(uint32_t*)(C + (size_t)row * Nld + col) =
                h2u(__floats2half2_rn(acc[mt][nt][0], acc[mt][nt][1]));
            *(uint32_t*)(C + (size_t)(row + 8) * Nld + col) =
                h2u(__floats2half2_rn(acc[mt][nt][2], acc[mt][nt][3]));
        }
    }
}

// ===========================================================================
// fp16 flash attention (unchanged). One block per (b,h), 8 warps, 2 CTAs/SM.
// ===========================================================================
#define SC     64
#define NCHUNK (SEQ / SC)                // 32
#define KVSTR  72
#define KBUF_H (64 * KVSTR)
#define VS_H   (2 * KBUF_H)
#define PS_H   (VS_H + 2 * KBUF_H)
#define PSTR   72
#define ATTN_SMEM ((PS_H + 8 * 16 * PSTR) * 2)   // 55296 B

__global__ __launch_bounds__(256, 2) void attn_mma(
    const __half* __restrict__ Q, const __half* __restrict__ KV,
    __half* __restrict__ O)
{
    extern __shared__ __align__(16) __half smh[];
    const uint32_t sbase = (uint32_t)__cvta_generic_to_shared(smh);
    const int tid  = threadIdx.x;
    const int wid  = tid >> 5;
    const int lane = tid & 31;
    const int lr = lane >> 2;
    const int lc = lane & 3;
    const int b = blockIdx.x >> 4;
    const int h = blockIdx.x & 15;

    const __half* kvb = KV + (size_t)b * SEQ * (2 * INNER) + h * DHEAD;

    uint32_t qa[4][4];
    {
        const __half* Qb = Q + ((size_t)(b * NLAT + wid * 16)) * INNER + h * DHEAD;
        const __half2 s2 = __float2half2_rn(0.125f);
        #pragma unroll
        for (int kk = 0; kk < 4; kk++) {
            const int d = kk * 16 + 2 * lc;
            __half2 v;
            v = *(const __half2*)(Qb + (size_t)lr * INNER + d);       qa[kk][0] = h2u(__hmul2(v, s2));
            v = *(const __half2*)(Qb + (size_t)(lr + 8) * INNER + d); qa[kk][1] = h2u(__hmul2(v, s2));
            v = *(const __half2*)(Qb + (size_t)lr * INNER + d + 8);       qa[kk][2] = h2u(__hmul2(v, s2));
            v = *(const __half2*)(Qb + (size_t)(lr + 8) * INNER + d + 8); qa[kk][3] = h2u(__hmul2(v, s2));
        }
    }

    float o[8][4];
    #pragma unroll
    for (int nt = 0; nt < 8; nt++)
        #pragma unroll
        for (int r = 0; r < 4; r++) o[nt][r] = 0.f;
    float m0 = -1e30f, m1 = -1e30f, l0 = 0.f, l1 = 0.f;

    auto load_chunk = [&](int s0, int buf) {
        #pragma unroll
        for (int i = 0; i < 2; i++) {
            const int slot = tid + i * 256;
            const int r = slot >> 3;
            const int c = slot & 7;
            const __half* gk = kvb + (size_t)(s0 + r) * (2 * INNER) + c * 8;
            uint32_t dk = sbase + (uint32_t)(buf * KBUF_H + r * KVSTR + c * 8) * 2;
            uint32_t dv = sbase + (uint32_t)(VS_H + buf * KBUF_H + r * KVSTR + c * 8) * 2;
            asm volatile("cp.async.cg.shared.global [%0], [%1], 16;" :: "r"(dk), "l"(gk));
            asm volatile("cp.async.cg.shared.global [%0], [%1], 16;" :: "r"(dv), "l"(gk + INNER));
        }
    };

    load_chunk(0, 0);
    asm volatile("cp.async.commit_group;" ::: "memory");

    __half* Ps = smh + PS_H + wid * (16 * PSTR);
    uint32_t* Pu = (uint32_t*)Ps;
    const int kRow = (lane & 7) + ((lane >> 4) << 3);
    const int kK   = ((lane >> 3) & 1) << 3;
    const int vmi = lane >> 3;
    const int vJ  = ((vmi & 1) << 3) + (lane & 7);
    const int vD  = (vmi >> 1) << 3;

    #pragma unroll 1
    for (int c = 0; c < NCHUNK; c++) {
        const int buf = c & 1;
        __syncthreads();
        if (c + 1 < NCHUNK) {
            load_chunk((c + 1) * SC, buf ^ 1);
            asm volatile("cp.async.commit_group;" ::: "memory");
            asm volatile("cp.async.wait_group 1;" ::: "memory");
        } else {
            asm volatile("cp.async.wait_group 0;" ::: "memory");
        }
        __syncthreads();

        const uint32_t Kb = sbase + (uint32_t)(buf * KBUF_H) * 2;
        const uint32_t Vb = sbase + (uint32_t)(VS_H + buf * KBUF_H) * 2;

        float sc[8][4];
        #pragma unroll
        for (int nt = 0; nt < 8; nt++)
            #pragma unroll
            for (int r = 0; r < 4; r++) sc[nt][r] = 0.f;

        #pragma unroll
        for (int kk = 0; kk < 4; kk++) {
            const int k16 = kk * 16;
            uint32_t bb[8][2];
            #pragma unroll
            for (int g = 0; g < 4; g++) {
                uint32_t ad = Kb + (uint32_t)((g * 16 + kRow) * KVSTR + k16 + kK) * 2;
                LDSM_X4(bb[2 * g][0], bb[2 * g][1], bb[2 * g + 1][0], bb[2 * g + 1][1], ad);
            }
            #pragma unroll
            for (int nt = 0; nt < 8; nt++)
                mma_fp16(sc[nt], qa[kk], bb[nt]);
        }

        float mx0 = -1e30f, mx1 = -1e30f;
        #pragma unroll
        for (int nt = 0; nt < 8; nt++) {
            mx0 = fmaxf(mx0, fmaxf(sc[nt][0], sc[nt][1]));
            mx1 = fmaxf(mx1, fmaxf(sc[nt][2], sc[nt][3]));
        }
        #pragma unroll
        for (int off = 1; off <= 2; off <<= 1) {
            mx0 = fmaxf(mx0, __shfl_xor_sync(0xffffffffu, mx0, off));
            mx1 = fmaxf(mx1, __shfl_xor_sync(0xffffffffu, mx1, off));
        }
        const float nm0 = fmaxf(m0, mx0);
        const float nm1 = fmaxf(m1, mx1);
        const float cr0 = __expf(m0 - nm0);
        const float cr1 = __expf(m1 - nm1);
        m0 = nm0; m1 = nm1;

        float rs0 = 0.f, rs1 = 0.f;
        #pragma unroll
        for (int nt = 0; nt < 8; nt++) {
            float p0 = __expf(sc[nt][0] - nm0);
            float p1 = __expf(sc[nt][1] - nm0);
            float p2 = __expf(sc[nt][2] - nm1);
            float p3 = __expf(sc[nt][3] - nm1);
            rs0 += p0 + p1;
            rs1 += p2 + p3;
            Pu[lr * (PSTR / 2) + nt * 4 + lc]       = h2u(__floats2half2_rn(p0, p1));
            Pu[(lr + 8) * (PSTR / 2) + nt * 4 + lc] = h2u(__floats2half2_rn(p2, p3));
        }
        #pragma unroll
        for (int off = 1; off <= 2; off <<= 1) {
            rs0 += __shfl_xor_sync(0xffffffffu, rs0, off);
            rs1 += __shfl_xor_sync(0xffffffffu, rs1, off);
        }
        l0 = l0 * cr0 + rs0;
        l1 = l1 * cr1 + rs1;
        #pragma unroll
        for (int nt = 0; nt < 8; nt++) {
            o[nt][0] *= cr0; o[nt][1] *= cr0;
            o[nt][2] *= cr1; o[nt][3] *= cr1;
        }
        __syncwarp();

        #pragma unroll
        for (int kk = 0; kk < 4; kk++) {
            uint32_t pa[4];
            pa[0] = Pu[lr * (PSTR / 2) + kk * 8 + lc];
            pa[1] = Pu[(lr + 8) * (PSTR / 2) + kk * 8 + lc];
            pa[2] = Pu[lr * (PSTR / 2) + kk * 8 + lc + 4];
            pa[3] = Pu[(lr + 8) * (PSTR / 2) + kk * 8 + lc + 4];
            uint32_t vb[8][2];
            #pragma unroll
            for (int g = 0; g < 4; g++) {
                uint32_t ad = Vb + (uint32_t)((kk * 16 + vJ) * KVSTR + g * 16 + vD) * 2;
                LDSM_X4_T(vb[2 * g][0], vb[2 * g][1], vb[2 * g + 1][0], vb[2 * g + 1][1], ad);
            }
            #pragma unroll
            for (int nt = 0; nt < 8; nt++)
                mma_fp16(o[nt], pa, vb[nt]);
        }
        __syncwarp();
    }

    const float inv0 = 1.f / l0;
    const float inv1 = 1.f / l1;
    __half* Ob = O + ((size_t)(b * NLAT + wid * 16)) * INNER + h * DHEAD;
    #pragma unroll
    for (int nt = 0; nt < 8; nt++) {
        const int col = nt * 8 + 2 * lc;
        *(uint32_t*)(Ob + (size_t)lr * INNER + col) =
            h2u(__floats2half2_rn(o[nt][0] * inv0, o[nt][1] * inv0));
        *(uint32_t*)(Ob + (size_t)(lr + 8) * INNER + col) =
            h2u(__floats2half2_rn(o[nt][2] * inv1, o[nt][3] * inv1));
    }
}

// ===========================================================================
// launch
// ===========================================================================
extern "C" void kernel_launch(void* const* d_in, const int* in_sizes, int n_in,
                              void* d_out, int out_size)
{
    (void)in_sizes; (void)n_in; (void)out_size;
    const float* x   = (const float*)d_in[0];
    const float* lat = (const float*)d_in[1];
    const float* gx  = (const float*)d_in[2];
    const float* bx  = (const float*)d_in[3];
    const float* gl  = (const float*)d_in[4];
    const float* bl  = (const float*)d_in[5];
    const float* Wq  = (const float*)d_in[6];
    const float* Wkv = (const float*)d_in[7];
    const float* Wo  = (const float*)d_in[8];
    float* out = (float*)d_out;

    __half *p_xn, *p_ln, *p_kv, *p_q, *p_att, *p_wq, *p_wkv, *p_wo;
    cudaGetSymbolAddress((void**)&p_xn,  g_xn);
    cudaGetSymbolAddress((void**)&p_ln,  g_ln);
    cudaGetSymbolAddress((void**)&p_kv,  g_kv);
    cudaGetSymbolAddress((void**)&p_q,   g_q);
    cudaGetSymbolAddress((void**)&p_att, g_att);
    cudaGetSymbolAddress((void**)&p_wq,  g_wq);
    cudaGetSymbolAddress((void**)&p_wkv, g_wkv);
    cudaGetSymbolAddress((void**)&p_wo,  g_wo);

    cudaFuncSetAttribute(gemm_h<__half>, cudaFuncAttributeMaxDynamicSharedMemorySize, GEMM_SMEM);
    cudaFuncSetAttribute(gemm_h<float>,  cudaFuncAttributeMaxDynamicSharedMemorySize, GEMM_SMEM);
    cudaFuncSetAttribute(gemm_h2,        cudaFuncAttributeMaxDynamicSharedMemorySize, GEMM2_SMEM);
    cudaFuncSetAttribute(attn_mma, cudaFuncAttributeMaxDynamicSharedMemorySize, ATTN_SMEM);

    const int rowsX = BATCH * SEQ;    // 32768
    const int rowsL = BATCH * NLAT;   // 2048

    ln_kernel<<<rowsX, 256>>>(x,   gx, bx, p_xn);
    ln_kernel<<<rowsL, 256>>>(lat, gl, bl, p_ln);

    h_convert3_kernel<<<(N4_WKV + 2 * N4_WQ) / 256, 256>>>(
        (const float4*)Wkv, (const float4*)Wq, (const float4*)Wo,
        (uint2*)p_wkv, (uint2*)p_wq, (uint2*)p_wo);

    // kv = xn @ Wkv^T : BK=64, 3-stage
    gemm_h2<<<dim3(2 * INNER / 128, rowsX / 128), 256, GEMM2_SMEM>>>(p_xn, p_wkv, p_kv, 2 * INNER);
    // q = ln @ Wq^T
    gemm_h<__half><<<dim3(INNER / 128, rowsL / 128), 256, GEMM_SMEM>>>(p_ln, p_wq, p_q, INNER);

    attn_mma<<<BATCH * HEADS, 256, ATTN_SMEM>>>(p_q, p_kv, p_att);

    gemm_h<float><<<dim3(DIMC / 128, rowsL / 128), 256, GEMM_SMEM>>>(p_att, p_wo, out, DIMC);
}

// round 17
// speedup vs baseline: 1.2652x; 1.0113x over previous
#include <cuda_runtime.h>
#include <cuda_fp16.h>
#include <cstdint>
#include <cstddef>

// ---------------------------------------------------------------------------
// PerceiverAttention: fp16 mma.sync GEMMs (BK=64 everywhere) + flash-attn.
// R17: R14 skeleton (no streams/events) + gemm_h2 for ALL three projections.
//   B=16, S=2048, M=128, DIM=1024, HEADS=16, DIM_HEAD=64, INNER=1024
// ---------------------------------------------------------------------------

#define DIMC     1024
#define BATCH    16
#define SEQ      2048
#define NLAT     128
#define HEADS    16
#define DHEAD    64
#define INNER    1024
#define LNEPS    1e-5f
#define GK       1024

__device__ __half g_xn [(size_t)BATCH * SEQ * DIMC];
__device__ __half g_ln [(size_t)BATCH * NLAT * DIMC];
__device__ __half g_kv [(size_t)BATCH * SEQ * 2 * INNER];
__device__ __half g_q  [(size_t)BATCH * NLAT * INNER];
__device__ __half g_att[(size_t)BATCH * NLAT * INNER];
__device__ __half g_wq [(size_t)INNER * DIMC];
__device__ __half g_wkv[(size_t)2 * INNER * DIMC];
__device__ __half g_wo [(size_t)DIMC * INNER];

// ---------------------------------------------------------------------------
// helpers
// ---------------------------------------------------------------------------
__device__ __forceinline__ void mma_fp16(
    float* c, const uint32_t* a, const uint32_t* b)
{
    asm volatile(
        "mma.sync.aligned.m16n8k16.row.col.f32.f16.f16.f32 "
        "{%0,%1,%2,%3}, {%4,%5,%6,%7}, {%8,%9}, {%0,%1,%2,%3};"
        : "+f"(c[0]), "+f"(c[1]), "+f"(c[2]), "+f"(c[3])
        : "r"(a[0]), "r"(a[1]), "r"(a[2]), "r"(a[3]), "r"(b[0]), "r"(b[1]));
}

#define LDSM_X4(r0, r1, r2, r3, addr) \
    asm volatile("ldmatrix.sync.aligned.m8n8.x4.shared.b16 {%0,%1,%2,%3}, [%4];" \
        : "=r"(r0), "=r"(r1), "=r"(r2), "=r"(r3) : "r"(addr))

#define LDSM_X4_T(r0, r1, r2, r3, addr) \
    asm volatile("ldmatrix.sync.aligned.m8n8.x4.trans.shared.b16 {%0,%1,%2,%3}, [%4];" \
        : "=r"(r0), "=r"(r1), "=r"(r2), "=r"(r3) : "r"(addr))

__device__ __forceinline__ uint32_t h2u(__half2 h) {
    return *reinterpret_cast<uint32_t*>(&h);
}

// ===========================================================================
// fp32 -> fp16 weight conversion (all three weights in ONE launch)
// ===========================================================================
#define N4_WKV 524288
#define N4_WQ  262144
__global__ __launch_bounds__(256) void h_convert3_kernel(
    const float4* __restrict__ wkv, const float4* __restrict__ wq,
    const float4* __restrict__ wo,
    uint2* __restrict__ dkv, uint2* __restrict__ dq, uint2* __restrict__ dwo)
{
    int i = blockIdx.x * 256 + threadIdx.x;
    const float4* src;
    uint2* dst;
    int j;
    if (i < N4_WKV)              { src = wkv; dst = dkv; j = i; }
    else if (i < N4_WKV + N4_WQ) { src = wq;  dst = dq;  j = i - N4_WKV; }
    else                         { src = wo;  dst = dwo; j = i - N4_WKV - N4_WQ; }
    float4 v = src[j];
    uint2 o;
    o.x = h2u(__floats2half2_rn(v.x, v.y));
    o.y = h2u(__floats2half2_rn(v.z, v.w));
    dst[j] = o;
}

// ===========================================================================
// LayerNorm (1024) -> fp16. One block (256 threads) per row.
// ===========================================================================
__global__ __launch_bounds__(256) void ln_kernel(
    const float* __restrict__ X, const float* __restrict__ G,
    const float* __restrict__ Bv, __half* __restrict__ Y)
{
    const int row = blockIdx.x;
    const int t = threadIdx.x;
    const float4* xr = (const float4*)(X + (size_t)row * DIMC);
    float4 v = xr[t];

    float s = v.x + v.y + v.z + v.w;
    float q = v.x * v.x + v.y * v.y + v.z * v.z + v.w * v.w;
    #pragma unroll
    for (int o = 16; o > 0; o >>= 1) {
        s += __shfl_xor_sync(0xffffffffu, s, o);
        q += __shfl_xor_sync(0xffffffffu, q, o);
    }
    __shared__ float rs[8], rq[8];
    __shared__ float s_mu, s_r;
    if ((t & 31) == 0) { rs[t >> 5] = s; rq[t >> 5] = q; }
    __syncthreads();
    if (t == 0) {
        float S = 0.f, Q = 0.f;
        #pragma unroll
        for (int w = 0; w < 8; w++) { S += rs[w]; Q += rq[w]; }
        float mu  = S * (1.f / DIMC);
        float var = Q * (1.f / DIMC) - mu * mu;
        s_mu = mu;
        s_r  = rsqrtf(var + LNEPS);
    }
    __syncthreads();
    const float mu = s_mu, r = s_r;

    float4 g = ((const float4*)G)[t];
    float4 b = ((const float4*)Bv)[t];
    uint2 o;
    o.x = h2u(__floats2half2_rn((v.x - mu) * r * g.x + b.x,
                                (v.y - mu) * r * g.y + b.y));
    o.y = h2u(__floats2half2_rn((v.z - mu) * r * g.z + b.z,
                                (v.w - mu) * r * g.w + b.w));
    ((uint2*)(Y + (size_t)row * DIMC))[t] = o;
}

// ===========================================================================
// 128x128 fp16 mma GEMM, BK=64, 3 stages. 8 warps, 2 CTAs/SM.
// 16 mainloop barriers, 64 mma per warp per barrier window.
// smem: 3 x (2 x 128 x 72) halves = 110592 B per CTA; 2 CTAs/SM.
// ===========================================================================
#define H2STR 72                          // 64 + 8 pad halves
#define TILE2_H (128 * H2STR)             // 9216 halves
#define STAGE2_H (2 * TILE2_H)            // 18432 halves (36864 B)
#define GEMM2_SMEM (3 * STAGE2_H * 2)     // 110592 B
#define KITERS2 (GK / 64)                 // 16

__device__ __forceinline__ void stage_copy_h2(
    const __half* __restrict__ Ab, const __half* __restrict__ Bb,
    uint32_t sA, uint32_t sB, int k0, int tid)
{
    #pragma unroll
    for (int i = 0; i < 4; i++) {
        const int slot = tid + i * 256;        // 0..1023
        const int r = slot >> 3;               // row 0..127
        const int c = slot & 7;                // 8-half chunk 0..7
        const __half* ga = Ab + (size_t)r * GK + k0 + c * 8;
        const __half* gb = Bb + (size_t)r * GK + k0 + c * 8;
        uint32_t da = sA + (uint32_t)(r * H2STR + c * 8) * 2;
        uint32_t db = sB + (uint32_t)(r * H2STR + c * 8) * 2;
        asm volatile("cp.async.cg.shared.global [%0], [%1], 16;" :: "r"(da), "l"(ga));
        asm volatile("cp.async.cg.shared.global [%0], [%1], 16;" :: "r"(db), "l"(gb));
    }
}

template <typename OutT>
__global__ __launch_bounds__(256, 2) void gemm_h2(
    const __half* __restrict__ A, const __half* __restrict__ B,
    OutT* __restrict__ C, int Nld)
{
    extern __shared__ __align__(16) __half smh[];
    const int tid  = threadIdx.x;
    const int wid  = tid >> 5;
    const int lane = tid & 31;
    const int wm = wid >> 2;
    const int wn = wid & 3;
    const int rowBase = blockIdx.y * 128;
    const int colBase = blockIdx.x * 128;
    const __half* Ab = A + (size_t)rowBase * GK;
    const __half* Bb = B + (size_t)colBase * GK;

    const uint32_t sbase = (uint32_t)__cvta_generic_to_shared(smh);

    float acc[4][4][4];
    #pragma unroll
    for (int i = 0; i < 4; i++)
        #pragma unroll
        for (int j = 0; j < 4; j++)
            #pragma unroll
            for (int r = 0; r < 4; r++) acc[i][j][r] = 0.f;

    // prologue: stages 0, 1
    #pragma unroll
    for (int s = 0; s < 2; s++) {
        stage_copy_h2(Ab, Bb, sbase + (s * STAGE2_H) * 2,
                      sbase + (s * STAGE2_H + TILE2_H) * 2, s * 64, tid);
        asm volatile("cp.async.commit_group;" ::: "memory");
    }

    const int lr = lane >> 2;
    const int lc = lane & 3;
    const int aRow = wm * 64 + (lane & 15);
    const int aK   = (lane >> 4) << 3;
    const int bRow = wn * 32 + (lane & 7) + ((lane >> 4) << 3);
    const int bK   = ((lane >> 3) & 1) << 3;

    int buf = 0;                   // stage t % 3
    #pragma unroll 1
    for (int t = 0; t < KITERS2; t++) {
        if (t < KITERS2 - 1)
            asm volatile("cp.async.wait_group 1;" ::: "memory");
        else
            asm volatile("cp.async.wait_group 0;" ::: "memory");
        __syncthreads();

        if (t + 2 < KITERS2) {
            int nb = buf + 2; if (nb >= 3) nb -= 3;
            stage_copy_h2(Ab, Bb, sbase + (nb * STAGE2_H) * 2,
                          sbase + (nb * STAGE2_H + TILE2_H) * 2, (t + 2) * 64, tid);
            asm volatile("cp.async.commit_group;" ::: "memory");
        }

        const uint32_t sAs = sbase + (buf * STAGE2_H) * 2;
        const uint32_t sBs = sAs + TILE2_H * 2;

        #pragma unroll
        for (int kk = 0; kk < 4; kk++) {
            const int k16 = kk * 16;
            uint32_t a[4][4], b[4][2];
            #pragma unroll
            for (int mt = 0; mt < 4; mt++) {
                uint32_t ad = sAs + (uint32_t)((aRow + mt * 16) * H2STR + k16 + aK) * 2;
                LDSM_X4(a[mt][0], a[mt][1], a[mt][2], a[mt][3], ad);
            }
            #pragma unroll
            for (int g = 0; g < 2; g++) {
                uint32_t bd = sBs + (uint32_t)((bRow + g * 16) * H2STR + k16 + bK) * 2;
                LDSM_X4(b[2 * g][0], b[2 * g][1], b[2 * g + 1][0], b[2 * g + 1][1], bd);
            }
            #pragma unroll
            for (int mt = 0; mt < 4; mt++)
                #pragma unroll
                for (int nt = 0; nt < 4; nt++)
                    mma_fp16(acc[mt][nt], a[mt], b[nt]);
        }
        if (++buf == 3) buf = 0;
    }

    #pragma unroll
    for (int mt = 0; mt < 4; mt++) {
        #pragma unroll
        for (int nt = 0; nt < 4; nt++) {
            const int row = rowBase + wm * 64 + mt * 16 + lr;
            const int col = colBase + wn * 32 + nt * 8 + 2 * lc;
            if constexpr (sizeof(OutT) == 2) {
                __half* Ch = (__half*)C;
                *(uint32_t*)(Ch + (size_t)row * Nld + col) =
                    h2u(__floats2half2_rn(acc[mt][nt][0], acc[mt][nt][1]));
                *(uint32_t*)(Ch + (size_t)(row + 8) * Nld + col) =
                    h2u(__floats2half2_rn(acc[mt][nt][2], acc[mt][nt][3]));
            } else {
                float* Cf = (float*)C;
                *(float2*)(Cf + (size_t)row * Nld + col) =
                    make_float2(acc[mt][nt][0], acc[mt][nt][1]);
                *(float2*)(Cf + (size_t)(row + 8) * Nld + col) =
                    make_float2(acc[mt][nt][2], acc[mt][nt][3]);
            }
        }
    }
}

// ===========================================================================
// fp16 flash attention (unchanged). One block per (b,h), 8 warps, 2 CTAs/SM.
// ===========================================================================
#define SC     64
#define NCHUNK (SEQ / SC)                // 32
#define KVSTR  72
#define KBUF_H (64 * KVSTR)
#define VS_H   (2 * KBUF_H)
#define PS_H   (VS_H + 2 * KBUF_H)
#define PSTR   72
#define ATTN_SMEM ((PS_H + 8 * 16 * PSTR) * 2)   // 55296 B

__global__ __launch_bounds__(256, 2) void attn_mma(
    const __half* __restrict__ Q, const __half* __restrict__ KV,
    __half* __restrict__ O)
{
    extern __shared__ __align__(16) __half smh[];
    const uint32_t sbase = (uint32_t)__cvta_generic_to_shared(smh);
    const int tid  = threadIdx.x;
    const int wid  = tid >> 5;
    const int lane = tid & 31;
    const int lr = lane >> 2;
    const int lc = lane & 3;
    const int b = blockIdx.x >> 4;
    const int h = blockIdx.x & 15;

    const __half* kvb = KV + (size_t)b * SEQ * (2 * INNER) + h * DHEAD;

    uint32_t qa[4][4];
    {
        const __half* Qb = Q + ((size_t)(b * NLAT + wid * 16)) * INNER + h * DHEAD;
        const __half2 s2 = __float2half2_rn(0.125f);
        #pragma unroll
        for (int kk = 0; kk < 4; kk++) {
            const int d = kk * 16 + 2 * lc;
            __half2 v;
            v = *(const __half2*)(Qb + (size_t)lr * INNER + d);       qa[kk][0] = h2u(__hmul2(v, s2));
            v = *(const __half2*)(Qb + (size_t)(lr + 8) * INNER + d); qa[kk][1] = h2u(__hmul2(v, s2));
            v = *(const __half2*)(Qb + (size_t)lr * INNER + d + 8);       qa[kk][2] = h2u(__hmul2(v, s2));
            v = *(const __half2*)(Qb + (size_t)(lr + 8) * INNER + d + 8); qa[kk][3] = h2u(__hmul2(v, s2));
        }
    }

    float o[8][4];
    #pragma unroll
    for (int nt = 0; nt < 8; nt++)
        #pragma unroll
        for (int r = 0; r < 4; r++) o[nt][r] = 0.f;
    float m0 = -1e30f, m1 = -1e30f, l0 = 0.f, l1 = 0.f;

    auto load_chunk = [&](int s0, int buf) {
        #pragma unroll
        for (int i = 0; i < 2; i++) {
            const int slot = tid + i * 256;
            const int r = slot >> 3;
            const int c = slot & 7;
            const __half* gk = kvb + (size_t)(s0 + r) * (2 * INNER) + c * 8;
            uint32_t dk = sbase + (uint32_t)(buf * KBUF_H + r * KVSTR + c * 8) * 2;
            uint32_t dv = sbase + (uint32_t)(VS_H + buf * KBUF_H + r * KVSTR + c * 8) * 2;
            asm volatile("cp.async.cg.shared.global [%0], [%1], 16;" :: "r"(dk), "l"(gk));
            asm volatile("cp.async.cg.shared.global [%0], [%1], 16;" :: "r"(dv), "l"(gk + INNER));
        }
    };

    load_chunk(0, 0);
    asm volatile("cp.async.commit_group;" ::: "memory");

    __half* Ps = smh + PS_H + wid * (16 * PSTR);
    uint32_t* Pu = (uint32_t*)Ps;
    const int kRow = (lane & 7) + ((lane >> 4) << 3);
    const int kK   = ((lane >> 3) & 1) << 3;
    const int vmi = lane >> 3;
    const int vJ  = ((vmi & 1) << 3) + (lane & 7);
    const int vD  = (vmi >> 1) << 3;

    #pragma unroll 1
    for (int c = 0; c < NCHUNK; c++) {
        const int buf = c & 1;
        __syncthreads();
        if (c + 1 < NCHUNK) {
            load_chunk((c + 1) * SC, buf ^ 1);
            asm volatile("cp.async.commit_group;" ::: "memory");
            asm volatile("cp.async.wait_group 1;" ::: "memory");
        } else {
            asm volatile("cp.async.wait_group 0;" ::: "memory");
        }
        __syncthreads();

        const uint32_t Kb = sbase + (uint32_t)(buf * KBUF_H) * 2;
        const uint32_t Vb = sbase + (uint32_t)(VS_H + buf * KBUF_H) * 2;

        float sc[8][4];
        #pragma unroll
        for (int nt = 0; nt < 8; nt++)
            #pragma unroll
            for (int r = 0; r < 4; r++) sc[nt][r] = 0.f;

        #pragma unroll
        for (int kk = 0; kk < 4; kk++) {
            const int k16 = kk * 16;
            uint32_t bb[8][2];
            #pragma unroll
            for (int g = 0; g < 4; g++) {
                uint32_t ad = Kb + (uint32_t)((g * 16 + kRow) * KVSTR + k16 + kK) * 2;
                LDSM_X4(bb[2 * g][0], bb[2 * g][1], bb[2 * g + 1][0], bb[2 * g + 1][1], ad);
            }
            #pragma unroll
            for (int nt = 0; nt < 8; nt++)
                mma_fp16(sc[nt], qa[kk], bb[nt]);
        }

        float mx0 = -1e30f, mx1 = -1e30f;
        #pragma unroll
        for (int nt = 0; nt < 8; nt++) {
            mx0 = fmaxf(mx0, fmaxf(sc[nt][0], sc[nt][1]));
            mx1 = fmaxf(mx1, fmaxf(sc[nt][2], sc[nt][3]));
        }
        #pragma unroll
        for (int off = 1; off <= 2; off <<= 1) {
            mx0 = fmaxf(mx0, __shfl_xor_sync(0xffffffffu, mx0, off));
            mx1 = fmaxf(mx1, __shfl_xor_sync(0xffffffffu, mx1, off));
        }
        const float nm0 = fmaxf(m0, mx0);
        const float nm1 = fmaxf(m1, mx1);
        const float cr0 = __expf(m0 - nm0);
        const float cr1 = __expf(m1 - nm1);
        m0 = nm0; m1 = nm1;

        float rs0 = 0.f, rs1 = 0.f;
        #pragma unroll
        for (int nt = 0; nt < 8; nt++) {
            float p0 = __expf(sc[nt][0] - nm0);
            float p1 = __expf(sc[nt][1] - nm0);
            float p2 = __expf(sc[nt][2] - nm1);
            float p3 = __expf(sc[nt][3] - nm1);
            rs0 += p0 + p1;
            rs1 += p2 + p3;
            Pu[lr * (PSTR / 2) + nt * 4 + lc]       = h2u(__floats2half2_rn(p0, p1));
            Pu[(lr + 8) * (PSTR / 2) + nt * 4 + lc] = h2u(__floats2half2_rn(p2, p3));
        }
        #pragma unroll
        for (int off = 1; off <= 2; off <<= 1) {
            rs0 += __shfl_xor_sync(0xffffffffu, rs0, off);
            rs1 += __shfl_xor_sync(0xffffffffu, rs1, off);
        }
        l0 = l0 * cr0 + rs0;
        l1 = l1 * cr1 + rs1;
        #pragma unroll
        for (int nt = 0; nt < 8; nt++) {
            o[nt][0] *= cr0; o[nt][1] *= cr0;
            o[nt][2] *= cr1; o[nt][3] *= cr1;
        }
        __syncwarp();

        #pragma unroll
        for (int kk = 0; kk < 4; kk++) {
            uint32_t pa[4];
            pa[0] = Pu[lr * (PSTR / 2) + kk * 8 + lc];
            pa[1] = Pu[(lr + 8) * (PSTR / 2) + kk * 8 + lc];
            pa[2] = Pu[lr * (PSTR / 2) + kk * 8 + lc + 4];
            pa[3] = Pu[(lr + 8) * (PSTR / 2) + kk * 8 + lc + 4];
            uint32_t vb[8][2];
            #pragma unroll
            for (int g = 0; g < 4; g++) {
                uint32_t ad = Vb + (uint32_t)((kk * 16 + vJ) * KVSTR + g * 16 + vD) * 2;
                LDSM_X4_T(vb[2 * g][0], vb[2 * g][1], vb[2 * g + 1][0], vb[2 * g + 1][1], ad);
            }
            #pragma unroll
            for (int nt = 0; nt < 8; nt++)
                mma_fp16(o[nt], pa, vb[nt]);
        }
        __syncwarp();
    }

    const float inv0 = 1.f / l0;
    const float inv1 = 1.f / l1;
    __half* Ob = O + ((size_t)(b * NLAT + wid * 16)) * INNER + h * DHEAD;
    #pragma unroll
    for (int nt = 0; nt < 8; nt++) {
        const int col = nt * 8 + 2 * lc;
        *(uint32_t*)(Ob + (size_t)lr * INNER + col) =
            h2u(__floats2half2_rn(o[nt][0] * inv0, o[nt][1] * inv0));
        *(uint32_t*)(Ob + (size_t)(lr + 8) * INNER + col) =
            h2u(__floats2half2_rn(o[nt][2] * inv1, o[nt][3] * inv1));
    }
}

// ===========================================================================
// launch (single stream, no host-object churn)
// ===========================================================================
extern "C" void kernel_launch(void* const* d_in, const int* in_sizes, int n_in,
                              void* d_out, int out_size)
{
    (void)in_sizes; (void)n_in; (void)out_size;
    const float* x   = (const float*)d_in[0];
    const float* lat = (const float*)d_in[1];
    const float* gx  = (const float*)d_in[2];
    const float* bx  = (const float*)d_in[3];
    const float* gl  = (const float*)d_in[4];
    const float* bl  = (const float*)d_in[5];
    const float* Wq  = (const float*)d_in[6];
    const float* Wkv = (const float*)d_in[7];
    const float* Wo  = (const float*)d_in[8];
    float* out = (float*)d_out;

    __half *p_xn, *p_ln, *p_kv, *p_q, *p_att, *p_wq, *p_wkv, *p_wo;
    cudaGetSymbolAddress((void**)&p_xn,  g_xn);
    cudaGetSymbolAddress((void**)&p_ln,  g_ln);
    cudaGetSymbolAddress((void**)&p_kv,  g_kv);
    cudaGetSymbolAddress((void**)&p_q,   g_q);
    cudaGetSymbolAddress((void**)&p_att, g_att);
    cudaGetSymbolAddress((void**)&p_wq,  g_wq);
    cudaGetSymbolAddress((void**)&p_wkv, g_wkv);
    cudaGetSymbolAddress((void**)&p_wo,  g_wo);

    cudaFuncSetAttribute(gemm_h2<__half>, cudaFuncAttributeMaxDynamicSharedMemorySize, GEMM2_SMEM);
    cudaFuncSetAttribute(gemm_h2<float>,  cudaFuncAttributeMaxDynamicSharedMemorySize, GEMM2_SMEM);
    cudaFuncSetAttribute(attn_mma, cudaFuncAttributeMaxDynamicSharedMemorySize, ATTN_SMEM);

    const int rowsX = BATCH * SEQ;    // 32768
    const int rowsL = BATCH * NLAT;   // 2048

    ln_kernel<<<rowsX, 256>>>(x,   gx, bx, p_xn);
    ln_kernel<<<rowsL, 256>>>(lat, gl, bl, p_ln);

    h_convert3_kernel<<<(N4_WKV + 2 * N4_WQ) / 256, 256>>>(
        (const float4*)Wkv, (const float4*)Wq, (const float4*)Wo,
        (uint2*)p_wkv, (uint2*)p_wq, (uint2*)p_wo);

    // kv = xn @ Wkv^T : BK=64, 3-stage
    gemm_h2<__half><<<dim3(2 * INNER / 128, rowsX / 128), 256, GEMM2_SMEM>>>(p_xn, p_wkv, p_kv, 2 * INNER);
    // q = ln @ Wq^T : BK=64
    gemm_h2<__half><<<dim3(INNER / 128, rowsL / 128), 256, GEMM2_SMEM>>>(p_ln, p_wq, p_q, INNER);

    attn_mma<<<BATCH * HEADS, 256, ATTN_SMEM>>>(p_q, p_kv, p_att);

    // out = att @ Wo^T : BK=64, fp32 out
    gemm_h2<float><<<dim3(DIMC / 128, rowsL / 128), 256, GEMM2_SMEM>>>(p_att, p_wo, out, DIMC);
}